// round 11
// baseline (speedup 1.0000x reference)
#include <cuda_runtime.h>
#include <cuda_bf16.h>
#include <math.h>
#include <stdint.h>

#define BQ   16
#define TT   1000
#define MEL  80
#define HID  512
#define NCLS 64
#define NROW (BQ*TT)

#define CLN  8       // CTAs per cluster  (8 clusters x 8 CTAs = 64 -- proven placement)
#define NCTA 64
#define BPC  2       // batch elements per cluster

#define WROWB 1040u                 // bf16 row stride bytes (1024 + 16 pad)
#define WMATB (64u*WROWB)           // 66560 B per matrix slice
#define DYNSM (2u*WMATB)            // 133120 B

// ---------------- scratch (static device globals; no allocations) ----------------
__device__ float g_be0[NROW*HID];
__device__ float g_be1[NROW*HID];
__device__ float g_h1 [NROW*HID];
__device__ float g_xs1[NROW];

__device__ __forceinline__ float sigm(float x){ return 1.0f/(1.0f+expf(-x)); }

__device__ __forceinline__ uint32_t smem_u32(const void* p){
  uint32_t a;
  asm("{ .reg .u64 t; cvta.to.shared.u64 t, %1; cvt.u32.u64 %0, t; }" : "=r"(a) : "l"(p));
  return a;
}
__device__ __forceinline__ uint32_t mapa32(uint32_t laddr, uint32_t rnk){
  uint32_t ra;
  asm("mapa.shared::cluster.u32 %0, %1, %2;" : "=r"(ra) : "r"(laddr), "r"(rnk));
  return ra;
}
__device__ __forceinline__ void st_clu_v4(uint32_t ra, float4 v){
  asm volatile("st.shared::cluster.v4.f32 [%0], {%1,%2,%3,%4};"
               :: "r"(ra), "f"(v.x), "f"(v.y), "f"(v.z), "f"(v.w) : "memory");
}
__device__ __forceinline__ void st_clu_v2(uint32_t ra, float a, float b){
  asm volatile("st.shared::cluster.v2.f32 [%0], {%1,%2};"
               :: "r"(ra), "f"(a), "f"(b) : "memory");
}
__device__ __forceinline__ void st_release_u32(uint32_t ra, uint32_t v){
  asm volatile("st.release.cluster.shared::cluster.u32 [%0], %1;"
               :: "r"(ra), "r"(v) : "memory");
}
__device__ __forceinline__ uint32_t ld_acq_u32(uint32_t la){
  uint32_t v;
  asm volatile("ld.acquire.cluster.shared::cta.u32 %0, [%1];"
               : "=r"(v) : "r"(la) : "memory");
  return v;
}
#define CLUSTER_SYNC() do{ \
  asm volatile("barrier.cluster.arrive.aligned;" ::: "memory"); \
  asm volatile("barrier.cluster.wait.aligned;"  ::: "memory"); }while(0)

// permuted float4-group position for x buffers: group g (=k/4) -> pos
__host__ __device__ __forceinline__ int xpos(int g){
  int j = g>>1;
  return ((j>>4)<<5) + ((g&1)<<4) + (j&15);
}

// ---------------- be0 = clip(feats/||feats||) @ B0^T ; xs1 = ||be0|| ----------------
__global__ __launch_bounds__(256) void k_be0(const float* __restrict__ feats,
                                             const float* __restrict__ B0){
  __shared__ float xn[16][MEL];
  __shared__ float snorm[16];
  __shared__ float sxs[16];
  int tid = threadIdx.x;
  int row0 = blockIdx.x*16;
  for (int i=tid;i<16*MEL;i+=256)
    xn[i/MEL][i%MEL] = feats[row0*MEL + i];
  __syncthreads();
  if (tid<16){
    float s=0.f;
    #pragma unroll
    for (int k=0;k<MEL;k++){ float v=xn[tid][k]; s+=v*v; }
    sxs[tid]=fmaxf(sqrtf(s),1e-6f);
    snorm[tid]=0.f;
  }
  __syncthreads();
  for (int i=tid;i<16*MEL;i+=256){
    int r=i/MEL;
    float v = xn[r][i%MEL]/sxs[r];
    xn[r][i%MEL] = fminf(fmaxf(v,-1.f),1.f);
  }
  __syncthreads();
  int n0=tid, n1=tid+256;
  float a0[16], a1_[16];
  #pragma unroll
  for (int r=0;r<16;r++){ a0[r]=0.f; a1_[r]=0.f; }
  for (int k=0;k<MEL;k+=4){
    float4 w0 = *(const float4*)&B0[n0*MEL+k];
    float4 w1 = *(const float4*)&B0[n1*MEL+k];
    #pragma unroll
    for (int r=0;r<16;r++){
      float4 x = *(const float4*)&xn[r][k];
      a0 [r] += w0.x*x.x + w0.y*x.y + w0.z*x.z + w0.w*x.w;
      a1_[r] += w1.x*x.x + w1.y*x.y + w1.z*x.z + w1.w*x.w;
    }
  }
  #pragma unroll
  for (int r=0;r<16;r++){
    g_be0[(row0+r)*HID+n0]=a0[r];
    g_be0[(row0+r)*HID+n1]=a1_[r];
    atomicAdd(&snorm[r], a0[r]*a0[r] + a1_[r]*a1_[r]);
  }
  __syncthreads();
  if (tid<16) g_xs1[row0+tid] = fmaxf(sqrtf(snorm[tid]),1e-6f);
}

// ---------------- be1 = clip(be0/xs1) @ B1^T ----------------
__global__ __launch_bounds__(256) void k_be1(const float* __restrict__ B1){
  __shared__ float xn[16][HID];
  __shared__ float sxs[16];
  int tid=threadIdx.x;
  int row0=blockIdx.x*16;
  if (tid<16) sxs[tid]=g_xs1[row0+tid];
  __syncthreads();
  for (int i=tid;i<16*HID;i+=256){
    int r=i>>9;
    float v = g_be0[row0*HID + i]/sxs[r];
    xn[r][i&511] = fminf(fmaxf(v,-1.f),1.f);
  }
  __syncthreads();
  int n0=tid, n1=tid+256;
  float a0[16], a1_[16];
  #pragma unroll
  for (int r=0;r<16;r++){ a0[r]=0.f; a1_[r]=0.f; }
  for (int k=0;k<HID;k+=4){
    float4 w0 = *(const float4*)&B1[n0*HID+k];
    float4 w1 = *(const float4*)&B1[n1*HID+k];
    #pragma unroll
    for (int r=0;r<16;r++){
      float4 x = *(const float4*)&xn[r][k];
      a0 [r] += w0.x*x.x + w0.y*x.y + w0.z*x.z + w0.w*x.w;
      a1_[r] += w1.x*x.x + w1.y*x.y + w1.z*x.z + w1.w*x.w;
    }
  }
  #pragma unroll
  for (int r=0;r<16;r++){
    g_be1[(row0+r)*HID+n0]=a0[r];
    g_be1[(row0+r)*HID+n1]=a1_[r];
  }
}

// ---------------- serial recurrence: DSMEM push + per-pair release-flag sync ------
// CTA `rank` owns rows [rank*64,+64). Weights bf16 in smem; x vectors exchanged by
// plain DSMEM stores (permuted conflict-free layout). Sync = monotonic step-counter
// flags: push warp w -> dest w, __syncwarp, lane0 st.release flag; consumer polls
// its 8 LOCAL flags with ld.acquire. No cluster barriers in the loop.
__device__ __forceinline__ void dot_bf16(const uint8_t* __restrict__ wsm,
                                         const uint8_t* __restrict__ xb,
                                         int rg, int kq, float* __restrict__ acc){
  const uint8_t* wr = wsm + (unsigned)(rg*4)*WROWB + (unsigned)kq*16u;
  #pragma unroll
  for (int m=0;m<4;m++){
    float4 xa0 = *(const float4*)(xb + (m*32+kq)*16);
    float4 xa1 = *(const float4*)(xb + (m*32+16+kq)*16);
    float4 xb0 = *(const float4*)(xb + 2048 + (m*32+kq)*16);
    float4 xb1 = *(const float4*)(xb + 2048 + (m*32+16+kq)*16);
    #pragma unroll
    for (int r=0;r<4;r++){
      uint4 w = *(const uint4*)(wr + (unsigned)r*WROWB + (unsigned)m*256u);
      float w0=__uint_as_float(w.x<<16), w1=__uint_as_float(w.x&0xffff0000u);
      float w2=__uint_as_float(w.y<<16), w3=__uint_as_float(w.y&0xffff0000u);
      float w4=__uint_as_float(w.z<<16), w5=__uint_as_float(w.z&0xffff0000u);
      float w6=__uint_as_float(w.w<<16), w7=__uint_as_float(w.w&0xffff0000u);
      acc[r*2+0] += w0*xa0.x + w1*xa0.y + w2*xa0.z + w3*xa0.w
                  + w4*xa1.x + w5*xa1.y + w6*xa1.z + w7*xa1.w;
      acc[r*2+1] += w0*xb0.x + w1*xb0.y + w2*xb0.z + w3*xb0.w
                  + w4*xb1.x + w5*xb1.y + w6*xb1.z + w7*xb1.w;
    }
  }
}

__global__ __launch_bounds__(256,1) __cluster_dims__(CLN,1,1)
void k_serial(const float* __restrict__ C1, const float* __restrict__ W1,
              const float* __restrict__ a1, const float* __restrict__ tau,
              const float* __restrict__ gam){
  extern __shared__ __align__(16) uint8_t dynsm[];
  uint8_t* wsmC = dynsm;                 // [64][WROWB] bf16
  uint8_t* wsmW = dynsm + WMATB;

  __shared__ __align__(16) float hbufP[BPC][HID];    // permuted h   (remote-written)
  __shared__ __align__(16) float ebufP[BPC][HID];    // permuted err (remote-written)
  __shared__ __align__(16) float estageP[BPC][64];
  __shared__ __align__(16) float hstageP[BPC][64];
  __shared__ float2 pout2[64];
  __shared__ __align__(8) float2 narr2[CLN];         // (n_b0,n_b1) from each src
  __shared__ float normloc[2][BPC];                  // ping-pong by step parity
  __shared__ float sa[64];
  __shared__ uint32_t eflags[CLN];                   // step counters, remote-written
  __shared__ uint32_t hflags[CLN];

  const int tid  = threadIdx.x;
  const int rank = blockIdx.x & (CLN-1);
  const int b0   = (blockIdx.x / CLN) * BPC;
  const int rg   = tid >> 4, kq = tid & 15;
  const float tauv = __ldg(&tau[0]), gamv = __ldg(&gam[0]);

  // -------- prologue: convert weight slices fp32 -> bf16 smem --------
  for (int i=tid; i<64*128; i+=256){
    int r=i>>7, q=i&127;
    float4 vc = __ldg((const float4*)&C1[(rank*64+r)*HID + q*4]);
    float4 vw = __ldg((const float4*)&W1[(rank*64+r)*HID + q*4]);
    __nv_bfloat162 c0 = __floats2bfloat162_rn(vc.x, vc.y);
    __nv_bfloat162 c1 = __floats2bfloat162_rn(vc.z, vc.w);
    __nv_bfloat162 w0 = __floats2bfloat162_rn(vw.x, vw.y);
    __nv_bfloat162 w1 = __floats2bfloat162_rn(vw.z, vw.w);
    uint2 uc; uc.x = *(uint32_t*)&c0; uc.y = *(uint32_t*)&c1;
    uint2 uw; uw.x = *(uint32_t*)&w0; uw.y = *(uint32_t*)&w1;
    *(uint2*)(wsmC + (unsigned)r*WROWB + (unsigned)q*8u) = uc;
    *(uint2*)(wsmW + (unsigned)r*WROWB + (unsigned)q*8u) = uw;
  }
  for (int i=tid;i<BPC*HID;i+=256) (&hbufP[0][0])[i]=0.f;
  if (tid<2*BPC) (&normloc[0][0])[tid]=0.f;
  if (tid<CLN){ eflags[tid]=0u; hflags[tid]=0u; }
  if (tid<64)  sa[tid] = sigm(__ldg(&a1[rank*64+tid]));
  __syncthreads();
  CLUSTER_SYNC();        // flags/buffers init visible before any peer push

  const uint32_t a_ebuf  = smem_u32(&ebufP[0][0]);
  const uint32_t a_hbuf  = smem_u32(&hbufP[0][0]);
  const uint32_t a_narr  = smem_u32(&narr2[0]);
  const uint32_t a_eflag = smem_u32(&eflags[0]);
  const uint32_t a_hflag = smem_u32(&hflags[0]);

  const int eb = tid & 1, erow = tid >> 1;             // epilogue mapping (tid<128)
  const uint32_t wp = tid >> 5, lane = tid & 31;       // push mapping: warp wp -> dest wp
  const int pb = lane >> 4, pq = lane & 15;
  const uint32_t e_off = (uint32_t)(pb*HID + xpos(rank*16 + pq)*4)*4u;
  // loop-invariant remote addresses
  const uint32_t raE  = mapa32(a_ebuf + e_off, wp);
  const uint32_t raH  = mapa32(a_hbuf + e_off, wp);
  const uint32_t raN  = mapa32(a_narr + (unsigned)rank*8u, wp);
  const uint32_t raEf = mapa32(a_eflag + (unsigned)rank*4u, wp);
  const uint32_t raHf = mapa32(a_hflag + (unsigned)rank*4u, wp);
  const int hk   = rank*64 + erow;
  const int hidx = eb*HID + xpos(hk>>2)*4 + (hk&3);

  // prefetch per-step scalars for t=0
  float xsv=1.f, be0v=0.f, be1v=0.f;
  if (tid<128){
    int bb = b0+eb;
    xsv  = __ldg(&g_xs1[bb*TT]);
    be0v = __ldg(&g_be0[(bb*TT)*HID + rank*64 + erow]);
  }

  for (int t=0;t<TT;t++){
    const int par = t&1;
    const uint32_t want = (uint32_t)(t+1);

    // ======== phase 1: p = h @ C1^T (own rows), err, norm partial ========
    {
      float acc[8] = {0.f,0.f,0.f,0.f,0.f,0.f,0.f,0.f};
      dot_bf16(wsmC, (const uint8_t*)&hbufP[0][0], rg, kq, acc);
      #pragma unroll
      for (int off=8; off; off>>=1)
        #pragma unroll
        for (int j=0;j<8;j++) acc[j] += __shfl_down_sync(0xffffffffu, acc[j], off);
      if (kq==0){
        #pragma unroll
        for (int j=0;j<4;j++) pout2[rg*4+j] = make_float2(acc[j*2], acc[j*2+1]);
      }
    }
    __syncthreads();
    if (tid<128){
      float pv = eb ? pout2[erow].y : pout2[erow].x;
      float p = tanhf(pv) * xsv;
      float e = be0v - p;
      estageP[eb][erow] = e;
      float q = e*e;
      #pragma unroll
      for (int off=16; off>=2; off>>=1) q += __shfl_xor_sync(0xffffffffu,q,off);
      if ((tid&31)<2) atomicAdd(&normloc[par][tid&1], q);
    }
    __syncthreads();
    // push err slice (+norm pair) to dest=wp; publish via release flag
    {
      st_clu_v4(raE, ((const float4*)estageP)[lane]);
      if (lane==0) st_clu_v2(raN, normloc[par][0], normloc[par][1]);
      __syncwarp();
      if (lane==0) st_release_u32(raEf, want);
    }
    if (tid<128)                    // be1 prefetch hides inside the flag wait
      be1v = __ldg(&g_be1[((b0+eb)*TT+t)*HID + rank*64 + erow]);
    if (tid<CLN){ while (ld_acq_u32(a_eflag + (unsigned)tid*4u) < want) {} }
    __syncthreads();

    // ======== phase 2: surprise, ee = err @ W1^T, h update ========
    {
      float acc[8] = {0.f,0.f,0.f,0.f,0.f,0.f,0.f,0.f};
      dot_bf16(wsmW, (const uint8_t*)&ebufP[0][0], rg, kq, acc);
      #pragma unroll
      for (int off=8; off; off>>=1)
        #pragma unroll
        for (int j=0;j<8;j++) acc[j] += __shfl_down_sync(0xffffffffu, acc[j], off);
      if (kq==0){
        #pragma unroll
        for (int j=0;j<4;j++) pout2[rg*4+j] = make_float2(acc[j*2], acc[j*2+1]);
      }
    }
    __syncthreads();
    if (tid<128){
      float n2 = 0.f;
      #pragma unroll
      for (int s=0;s<CLN;s++) n2 += eb ? narr2[s].y : narr2[s].x;
      float rel = fminf(sqrtf(n2)/xsv, 4.0f);
      float s = sigm((rel - tauv)/gamv);
      float hold = (&hbufP[0][0])[hidx];
      float eev = eb ? pout2[erow].y : pout2[erow].x;
      float ih = 0.2f*hold + 0.6f*be1v + 0.2f*s*eev;
      float g = s*sa[erow];
      float hn = hold*(1.f-g) + tanhf(ih)*g;
      hstageP[eb][erow] = hn;
      g_h1[((b0+eb)*TT+t)*HID + rank*64 + erow] = hn;
      if (tid<2) normloc[par^1][tid] = 0.f;            // reset other slot
    }
    __syncthreads();
    // push new h slice to dest=wp; publish via release flag
    {
      st_clu_v4(raH, ((const float4*)hstageP)[lane]);
      __syncwarp();
      if (lane==0) st_release_u32(raHf, want);
    }
    if (tid<128 && t+1<TT){         // next-step scalars hide inside the flag wait
      int bb = b0+eb;
      xsv  = __ldg(&g_xs1[bb*TT+t+1]);
      be0v = __ldg(&g_be0[(bb*TT+t+1)*HID + rank*64 + erow]);
    }
    if (tid<CLN){ while (ld_acq_u32(a_hflag + (unsigned)tid*4u) < want) {} }
    __syncthreads();
  }
}

// ---------------- head: out = [h1, be1] @ head_w^T + head_b ----------------
__global__ __launch_bounds__(256) void k_head(const float* __restrict__ hw,
                                              const float* __restrict__ hb,
                                              float* __restrict__ out){
  __shared__ float sh[8*1024];
  __shared__ float sred[4*8*64];
  int tid=threadIdx.x;
  int row0=blockIdx.x*8;
  for (int i=tid;i<8*1024;i+=256){
    int r=i>>10, j=i&1023;
    sh[i] = (j<512)? g_h1[(row0+r)*HID+j] : g_be1[(row0+r)*HID+(j-512)];
  }
  __syncthreads();
  int c=tid&63, q=tid>>6;
  float acc[8];
  #pragma unroll
  for (int r=0;r<8;r++) acc[r]=0.f;
  for (int k=q*256;k<q*256+256;k+=4){
    float4 w = *(const float4*)&hw[c*1024+k];
    #pragma unroll
    for (int r=0;r<8;r++){
      float4 x = *(const float4*)&sh[r*1024+k];
      acc[r] += w.x*x.x + w.y*x.y + w.z*x.z + w.w*x.w;
    }
  }
  #pragma unroll
  for (int r=0;r<8;r++) sred[(q*8+r)*64+c]=acc[r];
  __syncthreads();
  for (int i=tid;i<8*64;i+=256){
    int r=i>>6, cc=i&63;
    out[(row0+r)*NCLS+cc] = sred[r*64+cc] + sred[(8+r)*64+cc]
                          + sred[(16+r)*64+cc] + sred[(24+r)*64+cc] + __ldg(&hb[cc]);
  }
}

// ---------------- launch ----------------
extern "C" void kernel_launch(void* const* d_in, const int* in_sizes, int n_in,
                              void* d_out, int out_size){
  const float* feats=(const float*)d_in[0];
  const float* B0  =(const float*)d_in[2];
  const float* C1  =(const float*)d_in[7];
  const float* B1  =(const float*)d_in[8];
  const float* W1  =(const float*)d_in[9];
  const float* a1  =(const float*)d_in[10];
  const float* tau1=(const float*)d_in[11];
  const float* gam1=(const float*)d_in[12];
  const float* hw  =(const float*)d_in[13];
  const float* hb  =(const float*)d_in[14];
  float* out=(float*)d_out;

  static int smem_set = 0;
  if (!smem_set){
    cudaFuncSetAttribute(k_serial, cudaFuncAttributeMaxDynamicSharedMemorySize, DYNSM);
    smem_set = 1;
  }

  k_be0   <<<NROW/16,256>>>(feats,B0);
  k_be1   <<<NROW/16,256>>>(B1);
  k_serial<<<NCTA,256,DYNSM>>>(C1,W1,a1,tau1,gam1);
  k_head  <<<NROW/8,256>>>(hw,hb,out);
}